// round 17
// baseline (speedup 1.0000x reference)
#include <cuda_runtime.h>
#include <cuda_fp16.h>
#include <cstdint>

#define VOCAB 14
#define EMBED 10
#define HID   50
#define TLEN  2048
#define NBATCH 4096
#define NB    16             // batch rows per CTA (two independent n=8 groups)
#define KD    64             // 50 h-units + 14 one-hot
#define HSTR  72             // hbuf k-stride (halves)
#define SSTR  68             // stage row stride (floats)

// A fragments prepacked for mma.m16n8k16 row-major A.
// gAfrag[gt*4+kt][lane][r]: gt = global 16-row m-tile (0..15), kt = k-tile.
// Rows r=4u+g (i,f,o pre-scaled 0.5 for sigmoid-via-tanh); cols k<50=W_hh, k>=50=XT.
__device__ uint32_t gAfrag[64][32][4];
__device__ float gq[HID];
__device__ float gc0;

// ---------------------------------------------------------------------------
__device__ __forceinline__ float waug_val(int row, int k,
                                          const float* emb, const float* W_ih,
                                          const float* W_hh, const float* b_ih,
                                          const float* b_hh)
{
    int u = row >> 2, g = row & 3;
    if (u >= HID) return 0.f;
    int c = g * HID + u;
    float v;
    if (k < HID) {
        v = W_hh[c * HID + k];
    } else {
        int vo = k - HID;
        v = b_ih[c] + b_hh[c];
        #pragma unroll
        for (int e = 0; e < EMBED; e++)
            v += emb[vo * EMBED + e] * W_ih[c * EMBED + e];
    }
    return (g == 2) ? v : 0.5f * v;   // pre-scale i,f,o for sigp
}

__global__ void prep_kernel(const float* __restrict__ emb,
                            const float* __restrict__ W_ih,
                            const float* __restrict__ W_hh,
                            const float* __restrict__ b_ih,
                            const float* __restrict__ b_hh,
                            const float* __restrict__ W1,
                            const float* __restrict__ b1,
                            const float* __restrict__ W2,
                            const float* __restrict__ b2)
{
    int tid = threadIdx.x;

    for (int idx = tid; idx < 64 * 32 * 4; idx += blockDim.x) {
        int r    = idx & 3;
        int lane = (idx >> 2) & 31;
        int tile = idx >> 7;               // gt*4 + kt
        int gt = tile >> 2, kt = tile & 3;
        int gid = lane >> 2, t4 = lane & 3;
        int row_in = gid + ((r & 1) ? 8 : 0);
        int col_in = 2 * t4 + ((r >= 2) ? 8 : 0);
        int row = 16 * gt + row_in;
        int k   = 16 * kt + col_in;
        float v0 = waug_val(row, k,     emb, W_ih, W_hh, b_ih, b_hh);
        float v1 = waug_val(row, k + 1, emb, W_ih, W_hh, b_ih, b_hh);
        __half2 h2 = __floats2half2_rn(v0, v1);
        gAfrag[tile][lane][r] = *reinterpret_cast<uint32_t*>(&h2);
    }

    for (int u = tid; u < HID; u += blockDim.x) {
        float s = 0.f;
        for (int m = 0; m < HID; m++) s += W2[m] * W1[m * HID + u];
        gq[u] = s;
    }
    if (tid == 0) {
        float s = b2[0];
        for (int m = 0; m < HID; m++) s += W2[m] * b1[m];
        gc0 = s;
    }
}

// ---------------------------------------------------------------------------
__device__ __forceinline__ void mma16816(float d[4], const uint32_t a[4],
                                         const uint32_t b[2])
{
    asm("mma.sync.aligned.m16n8k16.row.col.f32.f16.f16.f32 "
        "{%0,%1,%2,%3}, {%4,%5,%6,%7}, {%8,%9}, {%0,%1,%2,%3};"
        : "+f"(d[0]), "+f"(d[1]), "+f"(d[2]), "+f"(d[3])
        : "r"(a[0]), "r"(a[1]), "r"(a[2]), "r"(a[3]), "r"(b[0]), "r"(b[1]));
}
__device__ __forceinline__ float tanhfast(float x) {
    float y; asm("tanh.approx.f32 %0, %1;" : "=f"(y) : "f"(x)); return y;
}
// gate pre-scaled by 0.5: sigma(2y) = 0.5*tanh(y)+0.5
__device__ __forceinline__ float sigp(float y) { return fmaf(0.5f, tanhfast(y), 0.5f); }

// ---------------------------------------------------------------------------
// CTA: 4 warps, 16 batches (two independent n=8 groups -> 2x ILP per step).
// gates[256x16] = A[256x64] @ h_aug[64x16]; A stationary in registers.
// Interleaved m-tile map: warp w owns global tiles {w, w+4, w+8, w+12} so
// live cell units are balanced 14/12/12/12 across warps (no idle warp).
// h_aug fp16 double-buffered in SMEM; one __syncthreads per step.
// ---------------------------------------------------------------------------
__global__ __launch_bounds__(128) void lstm_kernel(const int* __restrict__ tokens,
                                                   float* __restrict__ out)
{
    __shared__ __align__(16) __half hbuf[2][NB][HSTR];   // h_aug[n][k] x2 buffers
    __shared__ __align__(16) float  stage[4][NB][SSTR];  // per-warp D transpose stage
    __shared__ __align__(16) float  hfin[NB][52];
    __shared__ __align__(16) int    sTok[NB];

    const int tid  = threadIdx.x;
    const int wid  = tid >> 5, lane = tid & 31;
    const int gid  = lane >> 2, t4 = lane & 3;
    const int b0   = blockIdx.x * NB;

    for (int i = tid; i < 2 * NB * HSTR; i += 128)
        (&hbuf[0][0][0])[i] = __float2half(0.f);
    __syncthreads();

    int tcur = 0, pt0 = 0, pt1 = 0;
    if (wid == 0 && lane < NB) {
        tcur = __ldg(&tokens[(size_t)(b0 + lane) * TLEN]);
        sTok[lane] = tcur;
        hbuf[0][lane][HID + tcur] = __float2half(1.f);
        pt0 = tcur; pt1 = tcur;
    }

    // stationary A fragments: warp w takes global tiles mt*4 + w
    uint32_t A[4][4][4];
    {
        const uint4* src = reinterpret_cast<const uint4*>(gAfrag);
        #pragma unroll
        for (int mt = 0; mt < 4; mt++)
            #pragma unroll
            for (int kt = 0; kt < 4; kt++) {
                uint4 v = __ldg(src + ((mt * 4 + wid) * 4 + kt) * 32 + lane);
                A[mt][kt][0] = v.x; A[mt][kt][1] = v.y;
                A[mt][kt][2] = v.z; A[mt][kt][3] = v.w;
            }
    }

    // cell ownership: u_slot = lane>>1 (16 slots = 4 tiles x 4 units)
    const int u_slot = lane >> 1, q = lane & 1;
    const int u_glob = 16 * (u_slot >> 2) + 4 * wid + (u_slot & 3);
    const bool uok = (u_glob < HID);

    float h8[8], c8[8];
    #pragma unroll
    for (int i = 0; i < 8; i++) { h8[i] = 0.f; c8[i] = 0.f; }

    __syncthreads();

    for (int t = 0; t < TLEN; ++t) {
        const int p = t & 1;

        // B fragments for both groups (cols 0-7 and 8-15)
        uint32_t B[4][2], B2[4][2];
        {
            const __half* hb  = &hbuf[p][gid][0];
            const __half* hb2 = &hbuf[p][gid + 8][0];
            #pragma unroll
            for (int kt = 0; kt < 4; kt++) {
                B[kt][0]  = *reinterpret_cast<const uint32_t*>(hb  + kt * 16 + 2 * t4);
                B[kt][1]  = *reinterpret_cast<const uint32_t*>(hb  + kt * 16 + 2 * t4 + 8);
                B2[kt][0] = *reinterpret_cast<const uint32_t*>(hb2 + kt * 16 + 2 * t4);
                B2[kt][1] = *reinterpret_cast<const uint32_t*>(hb2 + kt * 16 + 2 * t4 + 8);
            }
        }
        int tnext = tcur;
        if (wid == 0 && lane < NB && t + 1 < TLEN)
            tnext = __ldg(&tokens[(size_t)(b0 + lane) * TLEN + t + 1]);

        // 32 HMMA: two independent accumulation chains (ILP)
        float d[4][4], e[4][4];
        #pragma unroll
        for (int mt = 0; mt < 4; mt++) {
            d[mt][0] = d[mt][1] = d[mt][2] = d[mt][3] = 0.f;
            e[mt][0] = e[mt][1] = e[mt][2] = e[mt][3] = 0.f;
            #pragma unroll
            for (int kt = 0; kt < 4; kt++) {
                mma16816(d[mt], A[mt][kt], B[kt]);
                mma16816(e[mt], A[mt][kt], B2[kt]);
            }
        }

        // transpose-stage both groups (conflict-free STS.32)
        #pragma unroll
        for (int mt = 0; mt < 4; mt++) {
            int rw = mt * 16 + gid;
            stage[wid][2*t4    ][rw]     = d[mt][0];
            stage[wid][2*t4 + 1][rw]     = d[mt][1];
            stage[wid][2*t4    ][rw + 8] = d[mt][2];
            stage[wid][2*t4 + 1][rw + 8] = d[mt][3];
            stage[wid][8 + 2*t4    ][rw]     = e[mt][0];
            stage[wid][8 + 2*t4 + 1][rw]     = e[mt][1];
            stage[wid][8 + 2*t4    ][rw + 8] = e[mt][2];
            stage[wid][8 + 2*t4 + 1][rw + 8] = e[mt][3];
        }
        __syncwarp();

        // cells: lane owns unit u_glob, batches {4q..4q+3} and {8+4q..8+4q+3}
        if (uok) {
            int4 ta = *reinterpret_cast<const int4*>(&sTok[4 * q]);
            int4 tb = *reinterpret_cast<const int4*>(&sTok[8 + 4 * q]);
            const int tks[8] = {ta.x, ta.y, ta.z, ta.w, tb.x, tb.y, tb.z, tb.w};
            #pragma unroll
            for (int bi = 0; bi < 8; bi++) {
                int n = (bi < 4) ? (4 * q + bi) : (4 + 4 * q + bi);   // +8 group offset
                float4 gv = *reinterpret_cast<const float4*>(&stage[wid][n][4 * u_slot]);
                float i = sigp(gv.x);
                float f = sigp(gv.y);
                float g = tanhfast(gv.z);
                float o = sigp(gv.w);
                float cn = fmaf(f, c8[bi], i * g);
                float hn = o * tanhfast(cn);
                if (tks[bi] != 0) { c8[bi] = cn; h8[bi] = hn; }
                hbuf[1 - p][n][u_glob] = __float2half_rn(h8[bi]);   // unconditional
            }
        }

        // token / one-hot maintenance for next step (buffer 1-p)
        if (wid == 0 && lane < NB) {
            if (p == 0) {
                hbuf[1][lane][HID + pt1] = __float2half(0.f);
                hbuf[1][lane][HID + tnext] = __float2half(1.f);
                pt1 = tnext;
            } else {
                hbuf[0][lane][HID + pt0] = __float2half(0.f);
                hbuf[0][lane][HID + tnext] = __float2half(1.f);
                pt0 = tnext;
            }
            sTok[lane] = tnext;
            tcur = tnext;
        }
        __syncthreads();
    }

    // head: out = sigmoid(c0 + q . h_final)  (h from fp32 registers)
    if (uok) {
        #pragma unroll
        for (int bi = 0; bi < 8; bi++) {
            int n = (bi < 4) ? (4 * q + bi) : (4 + 4 * q + bi);
            hfin[n][u_glob] = h8[bi];
        }
    }
    __syncthreads();
    if (tid < NB) {
        float s = gc0;
        #pragma unroll 10
        for (int k = 0; k < HID; k++) s += gq[k] * hfin[tid][k];
        out[b0 + tid] = 1.0f / (1.0f + __expf(-s));
    }
}

// ---------------------------------------------------------------------------
extern "C" void kernel_launch(void* const* d_in, const int* in_sizes, int n_in,
                              void* d_out, int out_size)
{
    const int*   tokens = (const int*)  d_in[0];
    const float* emb    = (const float*)d_in[1];
    const float* W_ih   = (const float*)d_in[2];
    const float* W_hh   = (const float*)d_in[3];
    const float* b_ih   = (const float*)d_in[4];
    const float* b_hh   = (const float*)d_in[5];
    const float* W1     = (const float*)d_in[6];
    const float* b1     = (const float*)d_in[7];
    const float* W2     = (const float*)d_in[8];
    const float* b2     = (const float*)d_in[9];
    float* out = (float*)d_out;

    prep_kernel<<<1, 256>>>(emb, W_ih, W_hh, b_ih, b_hh, W1, b1, W2, b2);
    lstm_kernel<<<NBATCH / NB, 128>>>(tokens, out);
}